// round 10
// baseline (speedup 1.0000x reference)
#include <cuda_runtime.h>

// Closed-form evaluation of the 20-qubit, depth-2 circuit (terminal form).
//
// Heisenberg-picture derivation: final CZ layer is diagonal and commutes with
// the measured Z_q, RY conjugation gives Z -> cZ - sX, CZ dresses X with
// neighbor Z's, and the RX-encoded vacuum gives <Z_j> = cos x_j, <X_j> = 0,
// factorizing over qubits:
//
//   feature_q = -<Z_q>,
//   <Z_q> = c2_q*(c1_q*cx_q) - s2_q*s1_q*cx_q * (c1_{q-1}*cx_{q-1}) * (c1_{q+1}*cx_{q+1})
//
// boundary neighbor factors = 1; logits = feature @ W^T + b.
// This collapses the 32 x 2^20-amplitude simulation (~50 GB traffic) to ~640 flops.
//
// 32 CTAs x 32 threads: block = batch element, lane = qubit (lanes 20..31 neutral).
// Swept and falsified alternatives: per-thread serial arrays (R1: local-mem
// spills), 1x1024 single CTA (R5: intra-SM MUFU/LSU serialization), f32 REDUX
// (R3: not in sm_103a ISA — integer only), fmaf/reorder micro-folds (R7).
// dur_us draws for this binary: {4.608, 4.608, 6.656, 6.880} — harness
// replay/clock noise on a ~0.4us kernel; all values are 32ns-tick multiples.
// Kernel is architecturally terminal: 18 regs, no spills, minimum-depth
// reduction, one warp per SM.

#define N_QUBITS 20

__global__ void __launch_bounds__(32, 1) quantum_classifier_warp(
    const float* __restrict__ x,      // (32, 20)
    const float* __restrict__ theta,  // (2, 20)
    const float* __restrict__ W,      // (2, 20)
    const float* __restrict__ b,      // (2,)
    float* __restrict__ out)          // (32, 2)
{
    const int w = blockIdx.x;    // batch element
    const int l = threadIdx.x;   // lane = qubit
    const bool active = (l < N_QUBITS);

    // Independent loads issued up front (overlapping latency).
    float b0 = 0.0f, b1 = 0.0f;
    if (l == 0) { b0 = b[0]; b1 = b[1]; }
    float th1 = active ? theta[l]            : 0.0f;
    float th2 = active ? theta[N_QUBITS + l] : 0.0f;
    float xv  = active ? x[w * N_QUBITS + l] : 0.0f;
    float w0  = active ? W[l]                : 0.0f;
    float w1  = active ? W[N_QUBITS + l]     : 0.0f;

    float s1, c1, s2, c2;
    __sincosf(th1, &s1, &c1);
    __sincosf(th2, &s2, &c2);
    float cx = __cosf(xv);       // inactive lanes: cos(0) = 1

    float g = c1 * cx;           // inactive lanes: g = 1 (neutral boundary)

    float left  = __shfl_up_sync(0xffffffffu, g, 1);
    if (l == 0) left = 1.0f;                              // no left neighbor
    float right = __shfl_down_sync(0xffffffffu, g, 1);    // lane 19 reads lane 20's g == 1

    float z = c2 * g - s2 * s1 * cx * left * right;
    float f = -z;                // feature_q = -<Z_q>; inactive lanes carry W = 0

    // Two independent butterfly chains — pipeline through the shuffle unit.
    float a0 = f * w0;
    float a1 = f * w1;
#pragma unroll
    for (int off = 16; off > 0; off >>= 1) {
        a0 += __shfl_xor_sync(0xffffffffu, a0, off);
        a1 += __shfl_xor_sync(0xffffffffu, a1, off);
    }

    if (l == 0) {
        float2 r = make_float2(a0 + b0, a1 + b1);
        *reinterpret_cast<float2*>(out + w * 2) = r;
    }
}

extern "C" void kernel_launch(void* const* d_in, const int* in_sizes, int n_in,
                              void* d_out, int out_size) {
    const float* x     = (const float*)d_in[0];  // (32, 20)
    const float* theta = (const float*)d_in[1];  // (2, 20)
    const float* W     = (const float*)d_in[2];  // (2, 20)
    const float* b     = (const float*)d_in[3];  // (2,)
    float* out = (float*)d_out;                  // (32, 2)

    quantum_classifier_warp<<<32, 32>>>(x, theta, W, b, out);
}

// round 11
// speedup vs baseline: 1.4931x; 1.4931x over previous
#include <cuda_runtime.h>

// Closed-form evaluation of the 20-qubit, depth-2 circuit.
//
// Heisenberg picture: final CZ layer commutes with Z_q; RY gives Z -> cZ - sX;
// CZ dresses X with neighbor Z's; RX-encoded vacuum gives <Z_j>=cos x_j, <X_j>=0:
//
//   feature_q = -<Z_q>,
//   <Z_q> = c2_q*(c1_q*cx_q) - s2_q*s1_q*cx_q * (c1_{q-1}*cx_{q-1}) * (c1_{q+1}*cx_{q+1})
//
// boundary factors = 1; logits = feature @ W^T + b. Collapses the 32 x 2^20
// simulation to ~640 flops.
//
// Layout experiment (R10): 8 CTAs x 128 threads — warp = batch element,
// lane = qubit, exactly 1 warp per SMSP (no R5-style MUFU/LSU pileup),
// but only 8 CTA launch commands per graph replay instead of 32.
// History: 32x32 drew {4.608, 4.608, 6.656, 6.880, 6.880}; 1x1024 drew 6.624;
// true kernel execution ~0.4us, remainder replay/launch overhead.

#define N_QUBITS 20

__global__ void __launch_bounds__(128, 1) quantum_classifier_warp(
    const float* __restrict__ x,      // (32, 20)
    const float* __restrict__ theta,  // (2, 20)
    const float* __restrict__ W,      // (2, 20)
    const float* __restrict__ b,      // (2,)
    float* __restrict__ out)          // (32, 2)
{
    const int w = (blockIdx.x << 2) + (threadIdx.x >> 5);  // batch element 0..31
    const int l = threadIdx.x & 31;                        // lane = qubit
    const bool active = (l < N_QUBITS);

    // Independent loads issued up front (overlapping latency).
    float b0 = 0.0f, b1 = 0.0f;
    if (l == 0) { b0 = b[0]; b1 = b[1]; }
    float th1 = active ? theta[l]            : 0.0f;
    float th2 = active ? theta[N_QUBITS + l] : 0.0f;
    float xv  = active ? x[w * N_QUBITS + l] : 0.0f;
    float w0  = active ? W[l]                : 0.0f;
    float w1  = active ? W[N_QUBITS + l]     : 0.0f;

    float s1, c1, s2, c2;
    __sincosf(th1, &s1, &c1);
    __sincosf(th2, &s2, &c2);
    float cx = __cosf(xv);       // inactive lanes: cos(0) = 1

    float g = c1 * cx;           // inactive lanes: g = 1 (neutral boundary)

    float left  = __shfl_up_sync(0xffffffffu, g, 1);
    if (l == 0) left = 1.0f;                              // no left neighbor
    float right = __shfl_down_sync(0xffffffffu, g, 1);    // lane 19 reads lane 20's g == 1

    float z = c2 * g - s2 * s1 * cx * left * right;
    float f = -z;                // feature_q = -<Z_q>; inactive lanes carry W = 0

    // Two independent butterfly chains — pipeline through the shuffle unit.
    float a0 = f * w0;
    float a1 = f * w1;
#pragma unroll
    for (int off = 16; off > 0; off >>= 1) {
        a0 += __shfl_xor_sync(0xffffffffu, a0, off);
        a1 += __shfl_xor_sync(0xffffffffu, a1, off);
    }

    if (l == 0) {
        float2 r = make_float2(a0 + b0, a1 + b1);
        *reinterpret_cast<float2*>(out + w * 2) = r;
    }
}

extern "C" void kernel_launch(void* const* d_in, const int* in_sizes, int n_in,
                              void* d_out, int out_size) {
    const float* x     = (const float*)d_in[0];  // (32, 20)
    const float* theta = (const float*)d_in[1];  // (2, 20)
    const float* W     = (const float*)d_in[2];  // (2, 20)
    const float* b     = (const float*)d_in[3];  // (2,)
    float* out = (float*)d_out;                  // (32, 2)

    quantum_classifier_warp<<<8, 128>>>(x, theta, W, b, out);
}

// round 12
// speedup vs baseline: 1.5035x; 1.0070x over previous
#include <cuda_runtime.h>

// Closed-form evaluation of the 20-qubit, depth-2 circuit.
//
// Heisenberg picture: final CZ layer commutes with Z_q; RY gives Z -> cZ - sX;
// CZ dresses X with neighbor Z's; RX-encoded vacuum gives <Z_j>=cos x_j, <X_j>=0:
//
//   feature_q = -<Z_q>,
//   <Z_q> = c2_q*(c1_q*cx_q) - s2_q*s1_q*cx_q * (c1_{q-1}*cx_{q-1}) * (c1_{q+1}*cx_{q+1})
//
// boundary factors = 1; logits = feature @ W^T + b. Collapses the 32 x 2^20
// simulation to ~640 flops.
//
// CTA-shape sweep (ncu kernel time): 32x32 -> 3.84-4.64us; 8x128 -> 3.49us;
// 1x1024 -> 4.64us (8 warps/SMSP MUFU/LSU pileup). R12 probes 4x256
// (2 warps/SMSP — contention still negligible, half the CTA launch commands).
// warp = batch element, lane = qubit (lanes 20..31 neutral).

#define N_QUBITS 20

__global__ void __launch_bounds__(256, 1) quantum_classifier_warp(
    const float* __restrict__ x,      // (32, 20)
    const float* __restrict__ theta,  // (2, 20)
    const float* __restrict__ W,      // (2, 20)
    const float* __restrict__ b,      // (2,)
    float* __restrict__ out)          // (32, 2)
{
    const int w = (blockIdx.x << 3) + (threadIdx.x >> 5);  // batch element 0..31
    const int l = threadIdx.x & 31;                        // lane = qubit
    const bool active = (l < N_QUBITS);

    // Independent loads issued up front (overlapping latency).
    float b0 = 0.0f, b1 = 0.0f;
    if (l == 0) { b0 = b[0]; b1 = b[1]; }
    float th1 = active ? theta[l]            : 0.0f;
    float th2 = active ? theta[N_QUBITS + l] : 0.0f;
    float xv  = active ? x[w * N_QUBITS + l] : 0.0f;
    float w0  = active ? W[l]                : 0.0f;
    float w1  = active ? W[N_QUBITS + l]     : 0.0f;

    float s1, c1, s2, c2;
    __sincosf(th1, &s1, &c1);
    __sincosf(th2, &s2, &c2);
    float cx = __cosf(xv);       // inactive lanes: cos(0) = 1

    float g = c1 * cx;           // inactive lanes: g = 1 (neutral boundary)

    float left  = __shfl_up_sync(0xffffffffu, g, 1);
    if (l == 0) left = 1.0f;                              // no left neighbor
    float right = __shfl_down_sync(0xffffffffu, g, 1);    // lane 19 reads lane 20's g == 1

    float z = c2 * g - s2 * s1 * cx * left * right;
    float f = -z;                // feature_q = -<Z_q>; inactive lanes carry W = 0

    // Two independent butterfly chains — pipeline through the shuffle unit.
    float a0 = f * w0;
    float a1 = f * w1;
#pragma unroll
    for (int off = 16; off > 0; off >>= 1) {
        a0 += __shfl_xor_sync(0xffffffffu, a0, off);
        a1 += __shfl_xor_sync(0xffffffffu, a1, off);
    }

    if (l == 0) {
        float2 r = make_float2(a0 + b0, a1 + b1);
        *reinterpret_cast<float2*>(out + w * 2) = r;
    }
}

extern "C" void kernel_launch(void* const* d_in, const int* in_sizes, int n_in,
                              void* d_out, int out_size) {
    const float* x     = (const float*)d_in[0];  // (32, 20)
    const float* theta = (const float*)d_in[1];  // (2, 20)
    const float* W     = (const float*)d_in[2];  // (2, 20)
    const float* b     = (const float*)d_in[3];  // (2,)
    float* out = (float*)d_out;                  // (32, 2)

    quantum_classifier_warp<<<4, 256>>>(x, theta, W, b, out);
}